// round 10
// baseline (speedup 1.0000x reference)
#include <cuda_runtime.h>
#include <cuda_bf16.h>
#include <cstdint>
#include <math.h>

#define Bsz 64
#define TT  512
#define Din 256
#define Hh  512
#define G   2048   /* 4*H */

typedef unsigned long long ull;
typedef __nv_bfloat16 bf16;

// ---------------- scratch (static device globals; no allocation) ----------------
__device__ float g_gx0 [(size_t)2*TT*Bsz*G];    // [d][t][b][4H]
__device__ float g_gx1f[(size_t)TT*Bsz*G];      // [t][b][4H]
__device__ float g_gx1b[Bsz*G];
__device__ float g_h1f[Bsz*Hh];                 // layer1 fwd h (final used)
__device__ float g_hb[Bsz*Hh];                  // layer1 bwd one-step hidden
__device__ unsigned g_bar[6];                   // {d0 cnt,gen, d1 cnt,gen, s1 cnt,gen}

// bf16 split operands for projection GEMMs
__device__ bf16 g_xhi[(size_t)TT*Bsz*Din],   g_xlo[(size_t)TT*Bsz*Din];
__device__ bf16 g_o0hi[(size_t)TT*Bsz*2*Hh], g_o0lo[(size_t)TT*Bsz*2*Hh];
__device__ bf16 g_w0hi[2*G*Din],  g_w0lo[2*G*Din];
__device__ bf16 g_w1hi[2*G*2*Hh], g_w1lo[2*G*2*Hh];

// h state in MMA A-fragment layout: [kt(32)][mt(4)][lane(32)][reg 0-3 hi, 4-7 lo]
__device__ uint32_t g_f0[2][2][32768];          // [dir][pingpong]
__device__ uint32_t g_f1[2][32768];             // layer1 fwd [pingpong]
// W_hh in MMA B-fragment layout, 16384 words per CTA: [kt32][nt4][lane32][b0h,b1h,b0l,b1l]
__device__ uint32_t g_wf0[2*64*16384];          // [dir][cta64]
__device__ uint32_t g_wf1[64*16384];            // [cta64]

__device__ __forceinline__ float sigf(float x) { return 1.0f / (1.0f + expf(-x)); }

// ---------------- mma.sync helpers ----------------
__device__ __forceinline__ uint32_t smem_u32(const void* p) {
    uint32_t a;
    asm("{ .reg .u64 t; cvta.to.shared.u64 t, %1; cvt.u32.u64 %0, t; }" : "=r"(a) : "l"(p));
    return a;
}
__device__ __forceinline__ void ldsm4(uint32_t* r, uint32_t addr) {
    asm volatile("ldmatrix.sync.aligned.m8n8.x4.shared.b16 {%0,%1,%2,%3}, [%4];"
                 : "=r"(r[0]), "=r"(r[1]), "=r"(r[2]), "=r"(r[3]) : "r"(addr));
}
__device__ __forceinline__ void mma16816(float* d, const uint32_t* a,
                                         uint32_t b0, uint32_t b1) {
    asm volatile(
        "mma.sync.aligned.m16n8k16.row.col.f32.bf16.bf16.f32 "
        "{%0,%1,%2,%3}, {%4,%5,%6,%7}, {%8,%9}, {%0,%1,%2,%3};"
        : "+f"(d[0]), "+f"(d[1]), "+f"(d[2]), "+f"(d[3])
        : "r"(a[0]), "r"(a[1]), "r"(a[2]), "r"(a[3]), "r"(b0), "r"(b1));
}

// ---------------- acquire/release grid barrier (h traffic is ldcg/stcg = L2) ----
__device__ __forceinline__ void grid_bar(unsigned* cnt, unsigned* gen,
                                         unsigned target, unsigned nCTA) {
    __syncthreads();
    if (threadIdx.x == 0) {
        unsigned prev;
        asm volatile("atom.add.acq_rel.gpu.global.u32 %0, [%1], %2;"
                     : "=r"(prev) : "l"(cnt), "r"(1u) : "memory");
        if (prev + 1u == nCTA * target) {
            asm volatile("st.release.gpu.global.u32 [%0], %1;" :: "l"(gen), "r"(target) : "memory");
        } else {
            unsigned v;
            do {
                asm volatile("ld.acquire.gpu.global.u32 %0, [%1];" : "=r"(v) : "l"(gen) : "memory");
            } while (v < target);
        }
    }
    __syncthreads();
}

__global__ void k_init() {
    int i = blockIdx.x * 256 + threadIdx.x;     // 512 blocks -> i < 131072
    if (i < 131072) (&g_f0[0][0][0])[i] = 0u;
    if (i < 65536)  (&g_f1[0][0])[i]    = 0u;
    if (i < 6)      g_bar[i] = 0u;
}

// ---------------- hi/lo + wfrag pack helpers ----------------
__device__ __forceinline__ void wfrag_pack(float wx, float wy, uint32_t& whi, uint32_t& wlo) {
    bf16 h0 = __float2bfloat16(wx), h1 = __float2bfloat16(wy);
    bf16 l0 = __float2bfloat16(wx - __bfloat162float(h0));
    bf16 l1 = __float2bfloat16(wy - __bfloat162float(h1));
    whi = (uint32_t)__bfloat16_as_ushort(h0) | ((uint32_t)__bfloat16_as_ushort(h1) << 16);
    wlo = (uint32_t)__bfloat16_as_ushort(l0) | ((uint32_t)__bfloat16_as_ushort(l1) << 16);
}

// ---------------- merged prep kernels (launch-count/order control) ----------------
// prep0 = split_x + split w_ih0 + wfrag0
__global__ void k_prep0(const float* __restrict__ x, const float* __restrict__ w_ih0,
                        const float* __restrict__ w_hh0) {
    const int blk = blockIdx.x, tid = threadIdx.x;
    if (blk < 32768) {                               // x[b][t][d] -> hi/lo [t][b][d]
        int i = blk * 256 + tid;
        int d = i & (Din - 1), t = (i >> 8) & (TT - 1), b = i >> 17;
        float v = x[i];
        bf16 h = __float2bfloat16(v);
        size_t o = ((size_t)t * Bsz + b) * Din + d;
        g_xhi[o] = h;
        g_xlo[o] = __float2bfloat16(v - __bfloat162float(h));
    } else if (blk < 36864) {                        // w_ih0 split
        int i = (blk - 32768) * 256 + tid;
        float v = w_ih0[i];
        bf16 h = __float2bfloat16(v);
        g_w0hi[i] = h;
        g_w0lo[i] = __float2bfloat16(v - __bfloat162float(h));
    } else {                                         // wfrag0
        int idx = (blk - 36864) * 256 + tid;         // < 1048576
        int d  = idx >> 19;
        int r  = (idx >> 8) & 2047;
        int k  = (idx & 255) * 2;
        int gg = r >> 9, jj = r & 511;
        int cta = jj >> 3, u = jj & 7;
        int ngl = gg * 8 + u, nt = ngl >> 3, nc = ngl & 7;
        int kt = k >> 4;
        int lane2 = (nc << 2) | ((k & 7) >> 1);
        int reg = ((k & 15) >= 8) ? 1 : 0;
        float2 wv = *(const float2*)(w_hh0 + ((size_t)d * G + r) * Hh + k);
        uint32_t whi, wlo; wfrag_pack(wv.x, wv.y, whi, wlo);
        size_t base = ((size_t)d * 64 + cta) * 16384 + ((size_t)(kt * 4 + nt) * 32 + lane2) * 4;
        g_wf0[base + reg]     = whi;
        g_wf0[base + reg + 2] = wlo;
    }
}

// prep1 = split w_ih1 + wfrag1 (64-CTA layout)
__global__ void k_prep1(const float* __restrict__ w_ih1, const float* __restrict__ w_hh1) {
    const int blk = blockIdx.x, tid = threadIdx.x;
    if (blk < 16384) {                               // w_ih1 split (4M elems)
        int i = blk * 256 + tid;
        float v = w_ih1[i];
        bf16 h = __float2bfloat16(v);
        g_w1hi[i] = h;
        g_w1lo[i] = __float2bfloat16(v - __bfloat162float(h));
    } else {                                         // wfrag1
        int idx = (blk - 16384) * 256 + tid;         // < 524288
        int r  = idx >> 8;
        int k  = (idx & 255) * 2;
        int gg = r >> 9, jj = r & 511;
        int cta = jj >> 3, u = jj & 7;
        int ngl = gg * 8 + u, nt = ngl >> 3, nc = ngl & 7;
        int kt = k >> 4;
        int lane2 = (nc << 2) | ((k & 7) >> 1);
        int reg = ((k & 15) >= 8) ? 1 : 0;
        float2 wv = *(const float2*)(w_hh1 + (size_t)r * Hh + k);
        uint32_t whi, wlo; wfrag_pack(wv.x, wv.y, whi, wlo);
        size_t base = (size_t)cta * 16384 + ((size_t)(kt * 4 + nt) * 32 + lane2) * 4;
        g_wf1[base + reg]     = whi;
        g_wf1[base + reg + 2] = wlo;
    }
}

// ---------------- HMMA bf16-split projection GEMM (unchanged, proven) -----------
#define MMSM (2 * 4 * 128 * 40 * 2 + 512)

__device__ __forceinline__ uint4 g_ld4(const bf16* __restrict__ src, int K,
                                       int row, int k0, int q, int rowsv) {
    if (row < rowsv)
        return *reinterpret_cast<const uint4*>(src + (size_t)row * K + k0 + q * 8);
    return make_uint4(0u, 0u, 0u, 0u);
}

__global__ void __launch_bounds__(256) k_mma_gemm(
    const bf16* __restrict__ Ahi, const bf16* __restrict__ Alo,
    const bf16* __restrict__ Bhi, const bf16* __restrict__ Blo,
    const float* __restrict__ bia, const float* __restrict__ bib,
    float* __restrict__ C, int M, int K)
{
    extern __shared__ __align__(16) char smx[];
    bf16*  sbase = (bf16*)smx;
    float* bsum  = (float*)(smx + 81920);
    const int tid = threadIdx.x, wid = tid >> 5, lane = tid & 31;
    const int bn = blockIdx.x << 7, bm = blockIdx.y << 7;
    const int wm = wid >> 2, wn = wid & 3;
    const int av = (M - bm < 128) ? (M - bm) : 128;

    if (tid < 128) bsum[tid] = bia[bn + tid] + bib[bn + tid];

    const bf16* gAh = Ahi + (size_t)bm * K;
    const bf16* gAl = Alo + (size_t)bm * K;
    const bf16* gBh = Bhi + (size_t)bn * K;
    const bf16* gBl = Blo + (size_t)bn * K;

    const int r0 = tid >> 2, qq = tid & 3;

    {
        uint4 v[4][2];
        v[0][0] = g_ld4(gAh, K, r0, 0, qq, av);  v[0][1] = g_ld4(gAh, K, r0+64, 0, qq, av);
        v[1][0] = g_ld4(gAl, K, r0, 0, qq, av);  v[1][1] = g_ld4(gAl, K, r0+64, 0, qq, av);
        v[2][0] = g_ld4(gBh, K, r0, 0, qq, 128); v[2][1] = g_ld4(gBh, K, r0+64, 0, qq, 128);
        v[3][0] = g_ld4(gBl, K, r0, 0, qq, 128); v[3][1] = g_ld4(gBl, K, r0+64, 0, qq, 128);
#pragma unroll
        for (int t2 = 0; t2 < 4; t2++) {
            bf16* d = sbase + t2 * 5120;
            *reinterpret_cast<uint4*>(d + r0 * 40 + qq * 8)        = v[t2][0];
            *reinterpret_cast<uint4*>(d + (r0 + 64) * 40 + qq * 8) = v[t2][1];
        }
    }
    __syncthreads();

    float acc[4][4][4];
#pragma unroll
    for (int mi = 0; mi < 4; mi++)
#pragma unroll
        for (int ni = 0; ni < 4; ni++)
#pragma unroll
            for (int r = 0; r < 4; r++) acc[mi][ni][r] = 0.0f;

    const uint32_t sbu  = smem_u32(sbase);
    const uint32_t arow = 2u * (((uint32_t)(lane & 15)) * 40u + ((uint32_t)(lane >> 4)) * 8u);
    const int NKB = K >> 5;

    for (int kb = 0; kb < NKB; kb++) {
        uint4 v[4][2];
        const bool pf = (kb + 1 < NKB);
        if (pf) {
            const int k0 = (kb + 1) << 5;
            v[0][0] = g_ld4(gAh, K, r0, k0, qq, av);  v[0][1] = g_ld4(gAh, K, r0+64, k0, qq, av);
            v[1][0] = g_ld4(gAl, K, r0, k0, qq, av);  v[1][1] = g_ld4(gAl, K, r0+64, k0, qq, av);
            v[2][0] = g_ld4(gBh, K, r0, k0, qq, 128); v[2][1] = g_ld4(gBh, K, r0+64, k0, qq, 128);
            v[3][0] = g_ld4(gBl, K, r0, k0, qq, 128); v[3][1] = g_ld4(gBl, K, r0+64, k0, qq, 128);
        }

        const uint32_t base = sbu + ((kb & 1) ? 40960u : 0u);
        const uint32_t aA = base + arow + (uint32_t)wm * 5120u;
        const uint32_t aB = base + 20480u + arow + (uint32_t)wn * 2560u;
#pragma unroll
        for (int kh = 0; kh < 2; kh++) {
            const uint32_t ko = (uint32_t)kh * 32u;
            uint32_t ah[4][4], al_[4][4], bh[2][4], bl_[2][4];
#pragma unroll
            for (int mi = 0; mi < 4; mi++) {
                ldsm4(ah[mi],  aA + (uint32_t)mi * 1280u + ko);
                ldsm4(al_[mi], aA + 10240u + (uint32_t)mi * 1280u + ko);
            }
#pragma unroll
            for (int nj = 0; nj < 2; nj++) {
                ldsm4(bh[nj],  aB + (uint32_t)nj * 1280u + ko);
                ldsm4(bl_[nj], aB + 10240u + (uint32_t)nj * 1280u + ko);
            }
#pragma unroll
            for (int mi = 0; mi < 4; mi++) {
#pragma unroll
                for (int ni = 0; ni < 4; ni++) {
                    const int nj = ni >> 1, sb_ = ni & 1;
                    mma16816(acc[mi][ni], ah[mi],  bh[nj][sb_], bh[nj][sb_ + 2]);
                    mma16816(acc[mi][ni], ah[mi],  bl_[nj][sb_], bl_[nj][sb_ + 2]);
                    mma16816(acc[mi][ni], al_[mi], bh[nj][sb_], bh[nj][sb_ + 2]);
                }
            }
        }

        if (pf) {
            bf16* d0 = sbase + ((kb + 1) & 1) * 20480;
#pragma unroll
            for (int t2 = 0; t2 < 4; t2++) {
                bf16* d = d0 + t2 * 5120;
                *reinterpret_cast<uint4*>(d + r0 * 40 + qq * 8)        = v[t2][0];
                *reinterpret_cast<uint4*>(d + (r0 + 64) * 40 + qq * 8) = v[t2][1];
            }
        }
        __syncthreads();
    }

#pragma unroll
    for (int mi = 0; mi < 4; mi++) {
#pragma unroll
        for (int ni = 0; ni < 4; ni++) {
            const int coll = wn * 32 + ni * 8 + (lane & 3) * 2;
            const int rowa = bm + wm * 64 + mi * 16 + (lane >> 2);
            const float bx = bsum[coll], by = bsum[coll + 1];
            if (rowa < M) {
                float2 p = make_float2(acc[mi][ni][0] + bx, acc[mi][ni][1] + by);
                *reinterpret_cast<float2*>(C + (size_t)rowa * G + bn + coll) = p;
            }
            if (rowa + 8 < M) {
                float2 p = make_float2(acc[mi][ni][2] + bx, acc[mi][ni][3] + by);
                *reinterpret_cast<float2*>(C + (size_t)(rowa + 8) * G + bn + coll) = p;
            }
        }
    }
}

// ---------------- persistent tensor-core LSTM scan (NU=8, 64 CTAs per barrier) --
// CTA owns 8 hidden units (N=32 gate cols), all 64 batches. gates = h @ Wslice^T
// via m16n8k16 bf16-split, K-split-4 across warps, A-fragments double-buffered.
template<bool L0>
__global__ void __launch_bounds__(256, 1) k_scan_mma() {
    constexpr int NT = 4, NU = 8, NP = 34;
    __shared__ float gd[4][64][NP];
    __shared__ float c_sm[64][NU];

    const int tid = threadIdx.x, wid = tid >> 5, lane = tid & 31;
    const int kh = wid >> 1, mh = wid & 1;
    const int tig = lane & 3, gid = lane >> 2;

    const int cta = blockIdx.x;                  // 0..63
    const int dir = L0 ? blockIdx.y : 0;
    const int rev = L0 ? dir : 0;
    const int jbase = cta * NU;

    const float* gx = L0 ? (g_gx0 + (size_t)dir * TT * Bsz * G) : g_gx1f;
    const uint4* wf4 = L0 ? ((const uint4*)g_wf0) + ((size_t)dir * 64 + cta) * 4096
                          : ((const uint4*)g_wf1) + (size_t)cta * 4096;
    uint32_t* f0 = L0 ? g_f0[dir][0] : g_f1[0];
    uint32_t* f1 = L0 ? g_f0[dir][1] : g_f1[1];
    unsigned* bc = L0 ? &g_bar[2 * dir] : &g_bar[4];
    unsigned* bg = bc + 1;

    for (int i = tid; i < 64 * NU; i += 256) ((float*)c_sm)[i] = 0.f;

    // pointwise role: thread -> (batch pb, unit pair ppi)
    const int pb  = tid >> 2;
    const int ppi = tid & 3;
    const int jg  = jbase + 2 * ppi;
    const int fc = jg & 15, fr = pb & 15, fmt = pb >> 4, fkt = jg >> 4;
    const int flane = ((fr & 7) << 2) | ((fc & 7) >> 1);
    const int freg  = ((fr >> 3) & 1) | (((fc >> 3) & 1) << 1);
    const int faddr = ((fkt * 4 + fmt) * 32 + flane) * 8 + freg;

    __syncthreads();

    for (int t = 0; t < TT; t++) {
        const int tt = rev ? (TT - 1 - t) : t;
        const uint32_t* fin = (t & 1) ? f1 : f0;
        uint32_t* fout = (t & 1) ? f0 : f1;

        // gate pre-activations (independent of h; issued first, consumed last)
        float2 pre[4];
        {
            const float* gp = gx + ((size_t)tt * Bsz + pb) * G + jg;
            pre[0] = __ldcs((const float2*)gp);
            pre[1] = __ldcs((const float2*)(gp + 512));
            pre[2] = __ldcs((const float2*)(gp + 1024));
            pre[3] = __ldcs((const float2*)(gp + 1536));
        }

        float acc[2][NT][4];
#pragma unroll
        for (int m2 = 0; m2 < 2; m2++)
#pragma unroll
            for (int nt = 0; nt < NT; nt++)
#pragma unroll
                for (int r = 0; r < 4; r++) acc[m2][nt][r] = 0.f;

        // A-fragment double buffer
        uint4 cAh[2], cAl[2];
        {
            const int kt0 = kh * 8;
#pragma unroll
            for (int m2 = 0; m2 < 2; m2++) {
                const uint32_t* ap = fin + ((size_t)(kt0 * 4 + mh * 2 + m2) * 32 + lane) * 8;
                cAh[m2] = __ldcg((const uint4*)ap);
                cAl[m2] = __ldcg((const uint4*)(ap + 4));
            }
        }

#pragma unroll
        for (int k8 = 0; k8 < 8; k8++) {
            const int kt = kh * 8 + k8;
            uint4 nAh[2], nAl[2];
            if (k8 < 7) {
#pragma unroll
                for (int m2 = 0; m2 < 2; m2++) {
                    const uint32_t* ap = fin + ((size_t)((kt + 1) * 4 + mh * 2 + m2) * 32 + lane) * 8;
                    nAh[m2] = __ldcg((const uint4*)ap);
                    nAl[m2] = __ldcg((const uint4*)(ap + 4));
                }
            }
            uint4 Bv[NT];
#pragma unroll
            for (int nt = 0; nt < NT; nt++)
                Bv[nt] = __ldg(wf4 + (size_t)(kt * NT + nt) * 32 + lane);
#pragma unroll
            for (int m2 = 0; m2 < 2; m2++) {
                uint32_t ah[4] = {cAh[m2].x, cAh[m2].y, cAh[m2].z, cAh[m2].w};
                uint32_t al[4] = {cAl[m2].x, cAl[m2].y, cAl[m2].z, cAl[m2].w};
#pragma unroll
                for (int nt = 0; nt < NT; nt++) {
                    mma16816(acc[m2][nt], ah, Bv[nt].x, Bv[nt].y);   // hi*hi
                    mma16816(acc[m2][nt], ah, Bv[nt].z, Bv[nt].w);   // hi*lo
                    mma16816(acc[m2][nt], al, Bv[nt].x, Bv[nt].y);   // lo*hi
                }
            }
            if (k8 < 7) {
#pragma unroll
                for (int m2 = 0; m2 < 2; m2++) { cAh[m2] = nAh[m2]; cAl[m2] = nAl[m2]; }
            }
        }

        // dump K-quarter partials to smem
#pragma unroll
        for (int m2 = 0; m2 < 2; m2++) {
            const int rb = (mh * 2 + m2) * 16 + gid;
#pragma unroll
            for (int nt = 0; nt < NT; nt++) {
                const int col = nt * 8 + tig * 2;
                *(float2*)&gd[kh][rb][col]     = make_float2(acc[m2][nt][0], acc[m2][nt][1]);
                *(float2*)&gd[kh][rb + 8][col] = make_float2(acc[m2][nt][2], acc[m2][nt][3]);
            }
        }
        __syncthreads();

        {
            float hv[2];
#pragma unroll
            for (int uu = 0; uu < 2; uu++) {
                const int u = 2 * ppi + uu;
                float gi = uu ? pre[0].y : pre[0].x;
                float gf = uu ? pre[1].y : pre[1].x;
                float gc = uu ? pre[2].y : pre[2].x;
                float go = uu ? pre[3].y : pre[3].x;
#pragma unroll
                for (int q = 0; q < 4; q++) {
                    gi += gd[q][pb][0 * NU + u];
                    gf += gd[q][pb][1 * NU + u];
                    gc += gd[q][pb][2 * NU + u];
                    go += gd[q][pb][3 * NU + u];
                }
                float cc = sigf(gf) * c_sm[pb][u] + sigf(gi) * tanhf(gc);
                float hh = sigf(go) * tanhf(cc);
                c_sm[pb][u] = cc;
                hv[uu] = hh;
            }
            bf16 h0h = __float2bfloat16(hv[0]);
            bf16 h1h = __float2bfloat16(hv[1]);
            bf16 h0l = __float2bfloat16(hv[0] - __bfloat162float(h0h));
            bf16 h1l = __float2bfloat16(hv[1] - __bfloat162float(h1h));
            uint32_t whi = (uint32_t)__bfloat16_as_ushort(h0h) | ((uint32_t)__bfloat16_as_ushort(h1h) << 16);
            uint32_t wlo = (uint32_t)__bfloat16_as_ushort(h0l) | ((uint32_t)__bfloat16_as_ushort(h1l) << 16);
            __stcg((unsigned int*)&fout[faddr], whi);
            __stcg((unsigned int*)&fout[faddr + 4], wlo);
            if (L0) {
                const size_t oo = ((size_t)tt * Bsz + pb) * (2 * Hh) + (size_t)dir * Hh + jg;
                __stcg((unsigned int*)&g_o0hi[oo], whi);
                __stcg((unsigned int*)&g_o0lo[oo], wlo);
            } else {
                g_h1f[(size_t)pb * Hh + jg]     = hv[0];
                g_h1f[(size_t)pb * Hh + jg + 1] = hv[1];
            }
        }
        grid_bar(bc, bg, (unsigned)(t + 1), 64u);
    }
}

// layer1 backward at t=T-1: first step of reverse scan from zero state
__global__ void k_l1bwd() {
    int i = blockIdx.x * 256 + threadIdx.x;
    int b = i >> 9, j = i & 511;
    const float* gxp = g_gx1b + b * G;
    float gi = gxp[j], gc = gxp[2 * Hh + j], go = gxp[3 * Hh + j];
    float c = sigf(gi) * tanhf(gc);
    float h = sigf(go) * tanhf(c);
    g_hb[b * Hh + j] = h;
}

// ---------------- layernorm + MLP head ----------------
__global__ void __launch_bounds__(256) k_head(
    const float* __restrict__ ln_g, const float* __restrict__ ln_b,
    const float* __restrict__ w1,   const float* __restrict__ b1,
    const float* __restrict__ w2,   const float* __restrict__ b2,
    float* __restrict__ out)
{
    int b = blockIdx.x, tid = threadIdx.x;
    __shared__ float v[1024];
    __shared__ float red[256];
    for (int i = tid; i < Hh; i += 256) {
        v[i]      = g_h1f[b * Hh + i];
        v[Hh + i] = g_hb[b * Hh + i];
    }
    __syncthreads();
    float s = 0.f;
    for (int i = tid; i < 1024; i += 256) s += v[i];
    red[tid] = s; __syncthreads();
    for (int st = 128; st > 0; st >>= 1) { if (tid < st) red[tid] += red[tid + st]; __syncthreads(); }
    float mu = red[0] * (1.0f / 1024.0f);
    __syncthreads();
    s = 0.f;
    for (int i = tid; i < 1024; i += 256) { float dd = v[i] - mu; s += dd * dd; }
    red[tid] = s; __syncthreads();
    for (int st = 128; st > 0; st >>= 1) { if (tid < st) red[tid] += red[tid + st]; __syncthreads(); }
    float rstd = rsqrtf(red[0] * (1.0f / 1024.0f) + 1e-5f);
    __syncthreads();
    for (int i = tid; i < 1024; i += 256) v[i] = (v[i] - mu) * rstd * ln_g[i] + ln_b[i];
    __syncthreads();
    float part = 0.f;
    for (int jj = tid; jj < Hh; jj += 256) {
        float acc = b1[jj];
        const float* wr = w1 + (size_t)jj * 1024;
#pragma unroll 4
        for (int k2 = 0; k2 < 1024; k2++) acc += v[k2] * wr[k2];
        part += fmaxf(acc, 0.f) * w2[jj];
    }
    red[tid] = part; __syncthreads();
    for (int st = 128; st > 0; st >>= 1) { if (tid < st) red[tid] += red[tid + st]; __syncthreads(); }
    if (tid == 0) out[b] = red[0] + b2[0];
}

// ---------------- launch ----------------
extern "C" void kernel_launch(void* const* d_in, const int* in_sizes, int n_in,
                              void* d_out, int out_size)
{
    (void)in_sizes; (void)n_in; (void)out_size;
    const float* x     = (const float*)d_in[0];
    const float* w_ih0 = (const float*)d_in[1];
    const float* w_hh0 = (const float*)d_in[2];
    const float* b_ih0 = (const float*)d_in[3];
    const float* b_hh0 = (const float*)d_in[4];
    const float* w_ih1 = (const float*)d_in[5];
    const float* w_hh1 = (const float*)d_in[6];
    const float* b_ih1 = (const float*)d_in[7];
    const float* b_hh1 = (const float*)d_in[8];
    const float* ln_g  = (const float*)d_in[9];
    const float* ln_b  = (const float*)d_in[10];
    const float* w1    = (const float*)d_in[11];
    const float* b1    = (const float*)d_in[12];
    const float* w2    = (const float*)d_in[13];
    const float* b2    = (const float*)d_in[14];
    float* out = (float*)d_out;

    cudaFuncSetAttribute(k_mma_gemm, cudaFuncAttributeMaxDynamicSharedMemorySize, MMSM);

    void *p_gx0, *p_gx1f, *p_gx1b;
    void *p_xhi, *p_xlo, *p_o0hi, *p_o0lo, *p_w0hi, *p_w0lo, *p_w1hi, *p_w1lo;
    cudaGetSymbolAddress(&p_gx0, g_gx0);
    cudaGetSymbolAddress(&p_gx1f, g_gx1f);
    cudaGetSymbolAddress(&p_gx1b, g_gx1b);
    cudaGetSymbolAddress(&p_xhi, g_xhi);   cudaGetSymbolAddress(&p_xlo, g_xlo);
    cudaGetSymbolAddress(&p_o0hi, g_o0hi); cudaGetSymbolAddress(&p_o0lo, g_o0lo);
    cudaGetSymbolAddress(&p_w0hi, g_w0hi); cudaGetSymbolAddress(&p_w0lo, g_w0lo);
    cudaGetSymbolAddress(&p_w1hi, g_w1hi); cudaGetSymbolAddress(&p_w1lo, g_w1lo);

    // launch order puts k_scan0 at index 5 for the ncu -s 5 -c 1 capture
    k_init<<<512, 256>>>();                               // 0
    k_prep0<<<40960, 256>>>(x, w_ih0, w_hh0);             // 1

    dim3 gg(16, 256);
    k_mma_gemm<<<gg, 256, MMSM>>>((bf16*)p_xhi, (bf16*)p_xlo,           // 2
                                  (bf16*)p_w0hi, (bf16*)p_w0lo,
                                  b_ih0, b_hh0, (float*)p_gx0, Bsz * TT, Din);
    k_mma_gemm<<<gg, 256, MMSM>>>((bf16*)p_xhi, (bf16*)p_xlo,           // 3
                                  (bf16*)p_w0hi + (size_t)G * Din, (bf16*)p_w0lo + (size_t)G * Din,
                                  b_ih0 + G, b_hh0 + G,
                                  (float*)p_gx0 + (size_t)TT * Bsz * G, Bsz * TT, Din);
    k_prep1<<<18432, 256>>>(w_ih1, w_hh1);                // 4

    // layer 0 bidirectional scan
    k_scan_mma<true><<<dim3(64, 2), 256>>>();             // 5  <- profiled

    // layer 1 fwd projection + bwd projection (only t = T-1)
    k_mma_gemm<<<gg, 256, MMSM>>>((bf16*)p_o0hi, (bf16*)p_o0lo,         // 6
                                  (bf16*)p_w1hi, (bf16*)p_w1lo,
                                  b_ih1, b_hh1, (float*)p_gx1f, Bsz * TT, 2 * Hh);
    k_mma_gemm<<<dim3(16, 1), 256, MMSM>>>(                              // 7
        (bf16*)p_o0hi + (size_t)(TT - 1) * Bsz * 2 * Hh,
        (bf16*)p_o0lo + (size_t)(TT - 1) * Bsz * 2 * Hh,
        (bf16*)p_w1hi + (size_t)G * 2 * Hh, (bf16*)p_w1lo + (size_t)G * 2 * Hh,
        b_ih1 + G, b_hh1 + G, (float*)p_gx1b, Bsz, 2 * Hh);

    // layer 1 forward scan (64 CTAs, NU=8)
    k_scan_mma<false><<<64, 256>>>();                     // 8

    k_l1bwd<<<128, 256>>>();                              // 9
    k_head<<<64, 256>>>(ln_g, ln_b, w1, b1, w2, b2, out); // 10
}

// round 11
// speedup vs baseline: 1.0027x; 1.0027x over previous
#include <cuda_runtime.h>
#include <cuda_bf16.h>
#include <cstdint>
#include <math.h>

#define Bsz 64
#define TT  512
#define Din 256
#define Hh  512
#define G   2048   /* 4*H */

typedef unsigned long long ull;
typedef __nv_bfloat16 bf16;

// ---------------- scratch (static device globals; no allocation) ----------------
__device__ float g_gx0 [(size_t)2*TT*Bsz*G];    // [d][t][b][4H]
__device__ float g_gx1f[(size_t)TT*Bsz*G];      // [t][b][4H]
__device__ float g_gx1b[Bsz*G];
__device__ float g_h1f[Bsz*Hh];                 // layer1 fwd h (final used)
__device__ float g_hb[Bsz*Hh];                  // layer1 bwd one-step hidden
__device__ unsigned g_flags[3*64*8];            // per-CTA step flags, 32B padded
                                                // dom0: scan0 d0, dom1: scan0 d1, dom2: scan1

// bf16 split operands for projection GEMMs
__device__ bf16 g_xhi[(size_t)TT*Bsz*Din],   g_xlo[(size_t)TT*Bsz*Din];
__device__ bf16 g_o0hi[(size_t)TT*Bsz*2*Hh], g_o0lo[(size_t)TT*Bsz*2*Hh];
__device__ bf16 g_w0hi[2*G*Din],  g_w0lo[2*G*Din];
__device__ bf16 g_w1hi[2*G*2*Hh], g_w1lo[2*G*2*Hh];

// h state in MMA A-fragment layout: [kt(32)][mt(4)][lane(32)][reg 0-3 hi, 4-7 lo]
__device__ uint32_t g_f0[2][2][32768];          // [dir][pingpong]
__device__ uint32_t g_f1[2][32768];             // layer1 fwd [pingpong]
// W_hh in MMA B-fragment layout, 16384 words per CTA: [kt32][nt4][lane32][b0h,b1h,b0l,b1l]
__device__ uint32_t g_wf0[2*64*16384];          // [dir][cta64]
__device__ uint32_t g_wf1[64*16384];            // [cta64]

__device__ __forceinline__ float sigf(float x) { return 1.0f / (1.0f + __expf(-x)); }
__device__ __forceinline__ float tanhfast(float x) {
    float e = __expf(-2.0f * fabsf(x));
    float r = (1.0f - e) / (1.0f + e);
    return copysignf(r, x);
}

// ---------------- mma.sync helpers ----------------
__device__ __forceinline__ uint32_t smem_u32(const void* p) {
    uint32_t a;
    asm("{ .reg .u64 t; cvta.to.shared.u64 t, %1; cvt.u32.u64 %0, t; }" : "=r"(a) : "l"(p));
    return a;
}
__device__ __forceinline__ void ldsm4(uint32_t* r, uint32_t addr) {
    asm volatile("ldmatrix.sync.aligned.m8n8.x4.shared.b16 {%0,%1,%2,%3}, [%4];"
                 : "=r"(r[0]), "=r"(r[1]), "=r"(r[2]), "=r"(r[3]) : "r"(addr));
}
__device__ __forceinline__ void mma16816(float* d, const uint32_t* a,
                                         uint32_t b0, uint32_t b1) {
    asm volatile(
        "mma.sync.aligned.m16n8k16.row.col.f32.bf16.bf16.f32 "
        "{%0,%1,%2,%3}, {%4,%5,%6,%7}, {%8,%9}, {%0,%1,%2,%3};"
        : "+f"(d[0]), "+f"(d[1]), "+f"(d[2]), "+f"(d[3])
        : "r"(a[0]), "r"(a[1]), "r"(a[2]), "r"(a[3]), "r"(b0), "r"(b1));
}

// ---------------- hi/lo + wfrag pack helpers ----------------
__device__ __forceinline__ void wfrag_pack(float wx, float wy, uint32_t& whi, uint32_t& wlo) {
    bf16 h0 = __float2bfloat16(wx), h1 = __float2bfloat16(wy);
    bf16 l0 = __float2bfloat16(wx - __bfloat162float(h0));
    bf16 l1 = __float2bfloat16(wy - __bfloat162float(h1));
    whi = (uint32_t)__bfloat16_as_ushort(h0) | ((uint32_t)__bfloat16_as_ushort(h1) << 16);
    wlo = (uint32_t)__bfloat16_as_ushort(l0) | ((uint32_t)__bfloat16_as_ushort(l1) << 16);
}

// ---------------- prep0 = split_x + split w_ih0 + wfrag0 + state/flag init ------
__global__ void k_prep0(const float* __restrict__ x, const float* __restrict__ w_ih0,
                        const float* __restrict__ w_hh0) {
    const int blk = blockIdx.x, tid = threadIdx.x;
    if (blk < 32768) {                               // x[b][t][d] -> hi/lo [t][b][d]
        int i = blk * 256 + tid;
        int d = i & (Din - 1), t = (i >> 8) & (TT - 1), b = i >> 17;
        float v = x[i];
        bf16 h = __float2bfloat16(v);
        size_t o = ((size_t)t * Bsz + b) * Din + d;
        g_xhi[o] = h;
        g_xlo[o] = __float2bfloat16(v - __bfloat162float(h));
    } else if (blk < 36864) {                        // w_ih0 split
        int i = (blk - 32768) * 256 + tid;
        float v = w_ih0[i];
        bf16 h = __float2bfloat16(v);
        g_w0hi[i] = h;
        g_w0lo[i] = __float2bfloat16(v - __bfloat162float(h));
    } else if (blk < 40960) {                        // wfrag0
        int idx = (blk - 36864) * 256 + tid;         // < 1048576
        int d  = idx >> 19;
        int r  = (idx >> 8) & 2047;
        int k  = (idx & 255) * 2;
        int gg = r >> 9, jj = r & 511;
        int cta = jj >> 3, u = jj & 7;
        int ngl = gg * 8 + u, nt = ngl >> 3, nc = ngl & 7;
        int kt = k >> 4;
        int lane2 = (nc << 2) | ((k & 7) >> 1);
        int reg = ((k & 15) >= 8) ? 1 : 0;
        float2 wv = *(const float2*)(w_hh0 + ((size_t)d * G + r) * Hh + k);
        uint32_t whi, wlo; wfrag_pack(wv.x, wv.y, whi, wlo);
        size_t base = ((size_t)d * 64 + cta) * 16384 + ((size_t)(kt * 4 + nt) * 32 + lane2) * 4;
        g_wf0[base + reg]     = whi;
        g_wf0[base + reg + 2] = wlo;
    } else {                                         // state + flag init
        int i = (blk - 40960) * 256 + tid;           // < 131072
        if (i < 131072) (&g_f0[0][0][0])[i] = 0u;
        if (i < 65536)  (&g_f1[0][0])[i]    = 0u;
        if (i < 3*64*8) g_flags[i] = 0u;
    }
}

// prep1 = split w_ih1 + wfrag1 (64-CTA layout)
__global__ void k_prep1(const float* __restrict__ w_ih1, const float* __restrict__ w_hh1) {
    const int blk = blockIdx.x, tid = threadIdx.x;
    if (blk < 16384) {                               // w_ih1 split (4M elems)
        int i = blk * 256 + tid;
        float v = w_ih1[i];
        bf16 h = __float2bfloat16(v);
        g_w1hi[i] = h;
        g_w1lo[i] = __float2bfloat16(v - __bfloat162float(h));
    } else {                                         // wfrag1
        int idx = (blk - 16384) * 256 + tid;         // < 524288
        int r  = idx >> 8;
        int k  = (idx & 255) * 2;
        int gg = r >> 9, jj = r & 511;
        int cta = jj >> 3, u = jj & 7;
        int ngl = gg * 8 + u, nt = ngl >> 3, nc = ngl & 7;
        int kt = k >> 4;
        int lane2 = (nc << 2) | ((k & 7) >> 1);
        int reg = ((k & 15) >= 8) ? 1 : 0;
        float2 wv = *(const float2*)(w_hh1 + (size_t)r * Hh + k);
        uint32_t whi, wlo; wfrag_pack(wv.x, wv.y, whi, wlo);
        size_t base = (size_t)cta * 16384 + ((size_t)(kt * 4 + nt) * 32 + lane2) * 4;
        g_wf1[base + reg]     = whi;
        g_wf1[base + reg + 2] = wlo;
    }
}

// ---------------- HMMA bf16-split projection GEMM (z-dim selects weight slice) --
#define MMSM (2 * 4 * 128 * 40 * 2 + 512)

__device__ __forceinline__ uint4 g_ld4(const bf16* __restrict__ src, int K,
                                       int row, int k0, int q, int rowsv) {
    if (row < rowsv)
        return *reinterpret_cast<const uint4*>(src + (size_t)row * K + k0 + q * 8);
    return make_uint4(0u, 0u, 0u, 0u);
}

__global__ void __launch_bounds__(256) k_mma_gemm(
    const bf16* __restrict__ Ahi, const bf16* __restrict__ Alo,
    const bf16* __restrict__ Bhi, const bf16* __restrict__ Blo,
    const float* __restrict__ bia, const float* __restrict__ bib,
    float* __restrict__ C, int M, int K,
    size_t bzs, size_t czs, int biazs)
{
    const int z = blockIdx.z;
    Bhi += (size_t)z * bzs; Blo += (size_t)z * bzs;
    C   += (size_t)z * czs;
    bia += (size_t)z * biazs; bib += (size_t)z * biazs;

    extern __shared__ __align__(16) char smx[];
    bf16*  sbase = (bf16*)smx;
    float* bsum  = (float*)(smx + 81920);
    const int tid = threadIdx.x, wid = tid >> 5, lane = tid & 31;
    const int bn = blockIdx.x << 7, bm = blockIdx.y << 7;
    const int wm = wid >> 2, wn = wid & 3;
    const int av = (M - bm < 128) ? (M - bm) : 128;

    if (tid < 128) bsum[tid] = bia[bn + tid] + bib[bn + tid];

    const bf16* gAh = Ahi + (size_t)bm * K;
    const bf16* gAl = Alo + (size_t)bm * K;
    const bf16* gBh = Bhi + (size_t)bn * K;
    const bf16* gBl = Blo + (size_t)bn * K;

    const int r0 = tid >> 2, qq = tid & 3;

    {
        uint4 v[4][2];
        v[0][0] = g_ld4(gAh, K, r0, 0, qq, av);  v[0][1] = g_ld4(gAh, K, r0+64, 0, qq, av);
        v[1][0] = g_ld4(gAl, K, r0, 0, qq, av);  v[1][1] = g_ld4(gAl, K, r0+64, 0, qq, av);
        v[2][0] = g_ld4(gBh, K, r0, 0, qq, 128); v[2][1] = g_ld4(gBh, K, r0+64, 0, qq, 128);
        v[3][0] = g_ld4(gBl, K, r0, 0, qq, 128); v[3][1] = g_ld4(gBl, K, r0+64, 0, qq, 128);
#pragma unroll
        for (int t2 = 0; t2 < 4; t2++) {
            bf16* d = sbase + t2 * 5120;
            *reinterpret_cast<uint4*>(d + r0 * 40 + qq * 8)        = v[t2][0];
            *reinterpret_cast<uint4*>(d + (r0 + 64) * 40 + qq * 8) = v[t2][1];
        }
    }
    __syncthreads();

    float acc[4][4][4];
#pragma unroll
    for (int mi = 0; mi < 4; mi++)
#pragma unroll
        for (int ni = 0; ni < 4; ni++)
#pragma unroll
            for (int r = 0; r < 4; r++) acc[mi][ni][r] = 0.0f;

    const uint32_t sbu  = smem_u32(sbase);
    const uint32_t arow = 2u * (((uint32_t)(lane & 15)) * 40u + ((uint32_t)(lane >> 4)) * 8u);
    const int NKB = K >> 5;

    for (int kb = 0; kb < NKB; kb++) {
        uint4 v[4][2];
        const bool pf = (kb + 1 < NKB);
        if (pf) {
            const int k0 = (kb + 1) << 5;
            v[0][0] = g_ld4(gAh, K, r0, k0, qq, av);  v[0][1] = g_ld4(gAh, K, r0+64, k0, qq, av);
            v[1][0] = g_ld4(gAl, K, r0, k0, qq, av);  v[1][1] = g_ld4(gAl, K, r0+64, k0, qq, av);
            v[2][0] = g_ld4(gBh, K, r0, k0, qq, 128); v[2][1] = g_ld4(gBh, K, r0+64, k0, qq, 128);
            v[3][0] = g_ld4(gBl, K, r0, k0, qq, 128); v[3][1] = g_ld4(gBl, K, r0+64, k0, qq, 128);
        }

        const uint32_t base = sbu + ((kb & 1) ? 40960u : 0u);
        const uint32_t aA = base + arow + (uint32_t)wm * 5120u;
        const uint32_t aB = base + 20480u + arow + (uint32_t)wn * 2560u;
#pragma unroll
        for (int kh = 0; kh < 2; kh++) {
            const uint32_t ko = (uint32_t)kh * 32u;
            uint32_t ah[4][4], al_[4][4], bh[2][4], bl_[2][4];
#pragma unroll
            for (int mi = 0; mi < 4; mi++) {
                ldsm4(ah[mi],  aA + (uint32_t)mi * 1280u + ko);
                ldsm4(al_[mi], aA + 10240u + (uint32_t)mi * 1280u + ko);
            }
#pragma unroll
            for (int nj = 0; nj < 2; nj++) {
                ldsm4(bh[nj],  aB + (uint32_t)nj * 1280u + ko);
                ldsm4(bl_[nj], aB + 10240u + (uint32_t)nj * 1280u + ko);
            }
#pragma unroll
            for (int mi = 0; mi < 4; mi++) {
#pragma unroll
                for (int ni = 0; ni < 4; ni++) {
                    const int nj = ni >> 1, sb_ = ni & 1;
                    mma16816(acc[mi][ni], ah[mi],  bh[nj][sb_], bh[nj][sb_ + 2]);
                    mma16816(acc[mi][ni], ah[mi],  bl_[nj][sb_], bl_[nj][sb_ + 2]);
                    mma16816(acc[mi][ni], al_[mi], bh[nj][sb_], bh[nj][sb_ + 2]);
                }
            }
        }

        if (pf) {
            bf16* d0 = sbase + ((kb + 1) & 1) * 20480;
#pragma unroll
            for (int t2 = 0; t2 < 4; t2++) {
                bf16* d = d0 + t2 * 5120;
                *reinterpret_cast<uint4*>(d + r0 * 40 + qq * 8)        = v[t2][0];
                *reinterpret_cast<uint4*>(d + (r0 + 64) * 40 + qq * 8) = v[t2][1];
            }
        }
        __syncthreads();
    }

#pragma unroll
    for (int mi = 0; mi < 4; mi++) {
#pragma unroll
        for (int ni = 0; ni < 4; ni++) {
            const int coll = wn * 32 + ni * 8 + (lane & 3) * 2;
            const int rowa = bm + wm * 64 + mi * 16 + (lane >> 2);
            const float bx = bsum[coll], by = bsum[coll + 1];
            if (rowa < M) {
                float2 p = make_float2(acc[mi][ni][0] + bx, acc[mi][ni][1] + by);
                *reinterpret_cast<float2*>(C + (size_t)rowa * G + bn + coll) = p;
            }
            if (rowa + 8 < M) {
                float2 p = make_float2(acc[mi][ni][2] + bx, acc[mi][ni][3] + by);
                *reinterpret_cast<float2*>(C + (size_t)(rowa + 8) * G + bn + coll) = p;
            }
        }
    }
}

// ---------------- persistent tensor-core LSTM scan, producer-flag sync ----------
// CTA owns 8 hidden units, all 64 batches. Warp kh waits only on the 16 producer
// CTAs of its own kt range (direct ld.acquire flag spin; no central atomic).
template<bool L0>
__global__ void __launch_bounds__(256, 1) k_scan_mma() {
    constexpr int NT = 4, NU = 8, NP = 34;
    __shared__ float gd[4][64][NP];
    __shared__ float c_sm[64][NU];

    const int tid = threadIdx.x, wid = tid >> 5, lane = tid & 31;
    const int kh = wid >> 1, mh = wid & 1;
    const int tig = lane & 3, gid = lane >> 2;

    const int cta = blockIdx.x;                  // 0..63
    const int dir = L0 ? blockIdx.y : 0;
    const int rev = L0 ? dir : 0;
    const int jbase = cta * NU;

    const float* gx = L0 ? (g_gx0 + (size_t)dir * TT * Bsz * G) : g_gx1f;
    const uint4* wf4 = L0 ? ((const uint4*)g_wf0) + ((size_t)dir * 64 + cta) * 4096
                          : ((const uint4*)g_wf1) + (size_t)cta * 4096;
    uint32_t* f0 = L0 ? g_f0[dir][0] : g_f1[0];
    uint32_t* f1 = L0 ? g_f0[dir][1] : g_f1[1];
    unsigned* dom = g_flags + (L0 ? dir * 512 : 1024);
    unsigned* flag_me = dom + cta * 8;
    // producer flag this warp polls: CTA 16*kh + (lane&15)
    const unsigned* flag_src = dom + (16 * kh + (lane & 15)) * 8;

    for (int i = tid; i < 64 * NU; i += 256) ((float*)c_sm)[i] = 0.f;

    // pointwise role: thread -> (batch pb, unit pair ppi)
    const int pb  = tid >> 2;
    const int ppi = tid & 3;
    const int jg  = jbase + 2 * ppi;
    const int fc = jg & 15, fr = pb & 15, fmt = pb >> 4, fkt = jg >> 4;
    const int flane = ((fr & 7) << 2) | ((fc & 7) >> 1);
    const int freg  = ((fr >> 3) & 1) | (((fc >> 3) & 1) << 1);
    const int faddr = ((fkt * 4 + fmt) * 32 + flane) * 8 + freg;

    __syncthreads();

    for (int t = 0; t < TT; t++) {
        const int tt = rev ? (TT - 1 - t) : t;
        const uint32_t* fin = (t & 1) ? f1 : f0;
        uint32_t* fout = (t & 1) ? f0 : f1;

        // gate pre-activations (independent of h; issued first, consumed last)
        float2 pre[4];
        {
            const float* gp = gx + ((size_t)tt * Bsz + pb) * G + jg;
            pre[0] = __ldcs((const float2*)gp);
            pre[1] = __ldcs((const float2*)(gp + 512));
            pre[2] = __ldcs((const float2*)(gp + 1024));
            pre[3] = __ldcs((const float2*)(gp + 1536));
        }

        // wait for this warp's producers to have published h^t (flag >= t)
        if (t > 0) {
            unsigned v;
            do {
                asm volatile("ld.acquire.gpu.global.u32 %0, [%1];"
                             : "=r"(v) : "l"(flag_src) : "memory");
            } while (v < (unsigned)t);
            __syncwarp();
        }

        float acc[2][NT][4];
#pragma unroll
        for (int m2 = 0; m2 < 2; m2++)
#pragma unroll
            for (int nt = 0; nt < NT; nt++)
#pragma unroll
                for (int r = 0; r < 4; r++) acc[m2][nt][r] = 0.f;

        // A-fragment double buffer
        uint4 cAh[2], cAl[2];
        {
            const int kt0 = kh * 8;
#pragma unroll
            for (int m2 = 0; m2 < 2; m2++) {
                const uint32_t* ap = fin + ((size_t)(kt0 * 4 + mh * 2 + m2) * 32 + lane) * 8;
                cAh[m2] = __ldcg((const uint4*)ap);
                cAl[m2] = __ldcg((const uint4*)(ap + 4));
            }
        }

#pragma unroll
        for (int k8 = 0; k8 < 8; k8++) {
            const int kt = kh * 8 + k8;
            uint4 nAh[2], nAl[2];
            if (k8 < 7) {
#pragma unroll
                for (int m2 = 0; m2 < 2; m2++) {
                    const uint32_t* ap = fin + ((size_t)((kt + 1) * 4 + mh * 2 + m2) * 32 + lane) * 8;
                    nAh[m2] = __ldcg((const uint4*)ap);
                    nAl[m2] = __ldcg((const uint4*)(ap + 4));
                }
            }
            uint4 Bv[NT];
#pragma unroll
            for (int nt = 0; nt < NT; nt++)
                Bv[nt] = __ldg(wf4 + (size_t)(kt * NT + nt) * 32 + lane);
#pragma unroll
            for (int m2 = 0; m2 < 2; m2++) {
                uint32_t ah[4] = {cAh[m2].x, cAh[m2].y, cAh[m2].z, cAh[m2].w};
                uint32_t al[4] = {cAl[m2].x, cAl[m2].y, cAl[m2].z, cAl[m2].w};
#pragma unroll
                for (int nt = 0; nt < NT; nt++) {
                    mma16816(acc[m2][nt], ah, Bv[nt].x, Bv[nt].y);   // hi*hi
                    mma16816(acc[m2][nt], ah, Bv[nt].z, Bv[nt].w);   // hi*lo
                    mma16816(acc[m2][nt], al, Bv[nt].x, Bv[nt].y);   // lo*hi
                }
            }
            if (k8 < 7) {
#pragma unroll
                for (int m2 = 0; m2 < 2; m2++) { cAh[m2] = nAh[m2]; cAl[m2] = nAl[m2]; }
            }
        }

        // dump K-quarter partials to smem
#pragma unroll
        for (int m2 = 0; m2 < 2; m2++) {
            const int rb = (mh * 2 + m2) * 16 + gid;
#pragma unroll
            for (int nt = 0; nt < NT; nt++) {
                const int col = nt * 8 + tig * 2;
                *(float2*)&gd[kh][rb][col]     = make_float2(acc[m2][nt][0], acc[m2][nt][1]);
                *(float2*)&gd[kh][rb + 8][col] = make_float2(acc[m2][nt][2], acc[m2][nt][3]);
            }
        }
        __syncthreads();

        // pointwise + h publish
        float hv[2];
        uint32_t whi, wlo;
        {
#pragma unroll
            for (int uu = 0; uu < 2; uu++) {
                const int u = 2 * ppi + uu;
                float gi = uu ? pre[0].y : pre[0].x;
                float gf = uu ? pre[1].y : pre[1].x;
                float gc = uu ? pre[2].y : pre[2].x;
                float go = uu ? pre[3].y : pre[3].x;
#pragma unroll
                for (int q = 0; q < 4; q++) {
                    gi += gd[q][pb][0 * NU + u];
                    gf += gd[q][pb][1 * NU + u];
                    gc += gd[q][pb][2 * NU + u];
                    go += gd[q][pb][3 * NU + u];
                }
                float cc = sigf(gf) * c_sm[pb][u] + sigf(gi) * tanhfast(gc);
                float hh = sigf(go) * tanhfast(cc);
                c_sm[pb][u] = cc;
                hv[uu] = hh;
            }
            bf16 h0h = __float2bfloat16(hv[0]);
            bf16 h1h = __float2bfloat16(hv[1]);
            bf16 h0l = __float2bfloat16(hv[0] - __bfloat162float(h0h));
            bf16 h1l = __float2bfloat16(hv[1] - __bfloat162float(h1h));
            whi = (uint32_t)__bfloat16_as_ushort(h0h) | ((uint32_t)__bfloat16_as_ushort(h1h) << 16);
            wlo = (uint32_t)__bfloat16_as_ushort(h0l) | ((uint32_t)__bfloat16_as_ushort(h1l) << 16);
            __stcg((unsigned int*)&fout[faddr], whi);
            __stcg((unsigned int*)&fout[faddr + 4], wlo);
        }
        __syncthreads();
        if (tid == 0) {
            asm volatile("st.release.gpu.global.u32 [%0], %1;"
                         :: "l"(flag_me), "r"((unsigned)(t + 1)) : "memory");
        }

        // side outputs off the critical path
        if (L0) {
            const size_t oo = ((size_t)tt * Bsz + pb) * (2 * Hh) + (size_t)dir * Hh + jg;
            __stcg((unsigned int*)&g_o0hi[oo], whi);
            __stcg((unsigned int*)&g_o0lo[oo], wlo);
        } else {
            g_h1f[(size_t)pb * Hh + jg]     = hv[0];
            g_h1f[(size_t)pb * Hh + jg + 1] = hv[1];
        }
    }
}

// layer1 backward at t=T-1: first step of reverse scan from zero state
__global__ void k_l1bwd() {
    int i = blockIdx.x * 256 + threadIdx.x;
    int b = i >> 9, j = i & 511;
    const float* gxp = g_gx1b + b * G;
    float gi = gxp[j], gc = gxp[2 * Hh + j], go = gxp[3 * Hh + j];
    float c = sigf(gi) * tanhfast(gc);
    float h = sigf(go) * tanhfast(c);
    g_hb[b * Hh + j] = h;
}

// ---------------- layernorm + MLP head ----------------
__global__ void __launch_bounds__(256) k_head(
    const float* __restrict__ ln_g, const float* __restrict__ ln_b,
    const float* __restrict__ w1,   const float* __restrict__ b1,
    const float* __restrict__ w2,   const float* __restrict__ b2,
    float* __restrict__ out)
{
    int b = blockIdx.x, tid = threadIdx.x;
    __shared__ float v[1024];
    __shared__ float red[256];
    for (int i = tid; i < Hh; i += 256) {
        v[i]      = g_h1f[b * Hh + i];
        v[Hh + i] = g_hb[b * Hh + i];
    }
    __syncthreads();
    float s = 0.f;
    for (int i = tid; i < 1024; i += 256) s += v[i];
    red[tid] = s; __syncthreads();
    for (int st = 128; st > 0; st >>= 1) { if (tid < st) red[tid] += red[tid + st]; __syncthreads(); }
    float mu = red[0] * (1.0f / 1024.0f);
    __syncthreads();
    s = 0.f;
    for (int i = tid; i < 1024; i += 256) { float dd = v[i] - mu; s += dd * dd; }
    red[tid] = s; __syncthreads();
    for (int st = 128; st > 0; st >>= 1) { if (tid < st) red[tid] += red[tid + st]; __syncthreads(); }
    float rstd = rsqrtf(red[0] * (1.0f / 1024.0f) + 1e-5f);
    __syncthreads();
    for (int i = tid; i < 1024; i += 256) v[i] = (v[i] - mu) * rstd * ln_g[i] + ln_b[i];
    __syncthreads();
    float part = 0.f;
    for (int jj = tid; jj < Hh; jj += 256) {
        float acc = b1[jj];
        const float* wr = w1 + (size_t)jj * 1024;
#pragma unroll 4
        for (int k2 = 0; k2 < 1024; k2++) acc += v[k2] * wr[k2];
        part += fmaxf(acc, 0.f) * w2[jj];
    }
    red[tid] = part; __syncthreads();
    for (int st = 128; st > 0; st >>= 1) { if (tid < st) red[tid] += red[tid + st]; __syncthreads(); }
    if (tid == 0) out[b] = red[0] + b2[0];
}

// ---------------- launch ----------------
extern "C" void kernel_launch(void* const* d_in, const int* in_sizes, int n_in,
                              void* d_out, int out_size)
{
    (void)in_sizes; (void)n_in; (void)out_size;
    const float* x     = (const float*)d_in[0];
    const float* w_ih0 = (const float*)d_in[1];
    const float* w_hh0 = (const float*)d_in[2];
    const float* b_ih0 = (const float*)d_in[3];
    const float* b_hh0 = (const float*)d_in[4];
    const float* w_ih1 = (const float*)d_in[5];
    const float* w_hh1 = (const float*)d_in[6];
    const float* b_ih1 = (const float*)d_in[7];
    const float* b_hh1 = (const float*)d_in[8];
    const float* ln_g  = (const float*)d_in[9];
    const float* ln_b  = (const float*)d_in[10];
    const float* w1    = (const float*)d_in[11];
    const float* b1    = (const float*)d_in[12];
    const float* w2    = (const float*)d_in[13];
    const float* b2    = (const float*)d_in[14];
    float* out = (float*)d_out;

    cudaFuncSetAttribute(k_mma_gemm, cudaFuncAttributeMaxDynamicSharedMemorySize, MMSM);

    void *p_gx0, *p_gx1f, *p_gx1b;
    void *p_xhi, *p_xlo, *p_o0hi, *p_o0lo, *p_w0hi, *p_w0lo, *p_w1hi, *p_w1lo;
    cudaGetSymbolAddress(&p_gx0, g_gx0);
    cudaGetSymbolAddress(&p_gx1f, g_gx1f);
    cudaGetSymbolAddress(&p_gx1b, g_gx1b);
    cudaGetSymbolAddress(&p_xhi, g_xhi);   cudaGetSymbolAddress(&p_xlo, g_xlo);
    cudaGetSymbolAddress(&p_o0hi, g_o0hi); cudaGetSymbolAddress(&p_o0lo, g_o0lo);
    cudaGetSymbolAddress(&p_w0hi, g_w0hi); cudaGetSymbolAddress(&p_w0lo, g_w0lo);
    cudaGetSymbolAddress(&p_w1hi, g_w1hi); cudaGetSymbolAddress(&p_w1lo, g_w1lo);

    // our launch #3 (0-based) is what ncu -s 5 profiles (2 harness kernels first)
    k_prep0<<<41472, 256>>>(x, w_ih0, w_hh0);                            // 0

    // layer 0 input projections, both directions via gridDim.z=2
    k_mma_gemm<<<dim3(16, 256, 2), 256, MMSM>>>(                         // 1
        (bf16*)p_xhi, (bf16*)p_xlo, (bf16*)p_w0hi, (bf16*)p_w0lo,
        b_ih0, b_hh0, (float*)p_gx0, Bsz * TT, Din,
        (size_t)G * Din, (size_t)TT * Bsz * G, G);

    k_prep1<<<18432, 256>>>(w_ih1, w_hh1);                               // 2

    // layer 0 bidirectional scan  <- profiled
    k_scan_mma<true><<<dim3(64, 2), 256>>>();                            // 3

    // layer 1 fwd projection + bwd projection (only t = T-1)
    k_mma_gemm<<<dim3(16, 256, 1), 256, MMSM>>>(                         // 4
        (bf16*)p_o0hi, (bf16*)p_o0lo, (bf16*)p_w1hi, (bf16*)p_w1lo,
        b_ih1, b_hh1, (float*)p_gx1f, Bsz * TT, 2 * Hh, 0, 0, 0);
    k_mma_gemm<<<dim3(16, 1, 1), 256, MMSM>>>(                           // 5
        (bf16*)p_o0hi + (size_t)(TT - 1) * Bsz * 2 * Hh,
        (bf16*)p_o0lo + (size_t)(TT - 1) * Bsz * 2 * Hh,
        (bf16*)p_w1hi + (size_t)G * 2 * Hh, (bf16*)p_w1lo + (size_t)G * 2 * Hh,
        b_ih1 + G, b_hh1 + G, (float*)p_gx1b, Bsz, 2 * Hh, 0, 0, 0);

    // layer 1 forward scan (64 CTAs, NU=8)
    k_scan_mma<false><<<64, 256>>>();                                    // 6

    k_l1bwd<<<128, 256>>>();                                             // 7
    k_head<<<64, 256>>>(ln_g, ln_b, w1, b1, w2, b2, out);                // 8
}

// round 12
// speedup vs baseline: 1.1499x; 1.1468x over previous
#include <cuda_runtime.h>
#include <cuda_bf16.h>
#include <cuda_fp16.h>
#include <cstdint>
#include <math.h>

#define Bsz 64
#define TT  512
#define Din 256
#define Hh  512
#define G   2048   /* 4*H */

typedef unsigned long long ull;
typedef __nv_bfloat16 bf16;

// ---------------- scratch (static device globals; no allocation) ----------------
__device__ float g_gx0 [(size_t)2*TT*Bsz*G];    // [d][t][b][4H]
__device__ float g_gx1f[(size_t)TT*Bsz*G];      // [t][b][4H]
__device__ float g_gx1b[Bsz*G];
__device__ float g_h1f[Bsz*Hh];                 // layer1 fwd h (final used)
__device__ float g_hb[Bsz*Hh];                  // layer1 bwd one-step hidden
__device__ unsigned g_flags[3*64*8];            // per-CTA step flags, 32B padded

// bf16 split operands for projection GEMMs (projections stay 3-term bf16)
__device__ bf16 g_xhi[(size_t)TT*Bsz*Din],   g_xlo[(size_t)TT*Bsz*Din];
__device__ bf16 g_o0hi[(size_t)TT*Bsz*2*Hh], g_o0lo[(size_t)TT*Bsz*2*Hh];
__device__ bf16 g_w0hi[2*G*Din],  g_w0lo[2*G*Din];
__device__ bf16 g_w1hi[2*G*2*Hh], g_w1lo[2*G*2*Hh];

// h state in MMA A-fragment layout (fp16, single term):
//   [kt(32)][mt(4)][lane(32)][reg0-3]  (4 words per lane-slot)
__device__ uint32_t g_f0[2][2][16384];          // [dir][pingpong]
__device__ uint32_t g_f1[2][16384];             // layer1 fwd [pingpong]
// W_hh in MMA B-fragment layout (fp16 hi/lo 2-term), 16384 words per CTA:
//   [kt32][nt4][lane32][b0h,b1h,b0l,b1l]
__device__ uint32_t g_wf0[2*64*16384];          // [dir][cta64]
__device__ uint32_t g_wf1[64*16384];            // [cta64]

__device__ __forceinline__ float sigf(float x) { return 1.0f / (1.0f + __expf(-x)); }
__device__ __forceinline__ float tanhfast(float x) {
    float e = __expf(-2.0f * fabsf(x));
    float r = (1.0f - e) / (1.0f + e);
    return copysignf(r, x);
}

// ---------------- mma.sync helpers ----------------
__device__ __forceinline__ uint32_t smem_u32(const void* p) {
    uint32_t a;
    asm("{ .reg .u64 t; cvta.to.shared.u64 t, %1; cvt.u32.u64 %0, t; }" : "=r"(a) : "l"(p));
    return a;
}
__device__ __forceinline__ void ldsm4(uint32_t* r, uint32_t addr) {
    asm volatile("ldmatrix.sync.aligned.m8n8.x4.shared.b16 {%0,%1,%2,%3}, [%4];"
                 : "=r"(r[0]), "=r"(r[1]), "=r"(r[2]), "=r"(r[3]) : "r"(addr));
}
__device__ __forceinline__ void mma16816(float* d, const uint32_t* a,
                                         uint32_t b0, uint32_t b1) {
    asm volatile(
        "mma.sync.aligned.m16n8k16.row.col.f32.bf16.bf16.f32 "
        "{%0,%1,%2,%3}, {%4,%5,%6,%7}, {%8,%9}, {%0,%1,%2,%3};"
        : "+f"(d[0]), "+f"(d[1]), "+f"(d[2]), "+f"(d[3])
        : "r"(a[0]), "r"(a[1]), "r"(a[2]), "r"(a[3]), "r"(b0), "r"(b1));
}
__device__ __forceinline__ void mma16816h(float* d, const uint32_t* a,
                                          uint32_t b0, uint32_t b1) {
    asm volatile(
        "mma.sync.aligned.m16n8k16.row.col.f32.f16.f16.f32 "
        "{%0,%1,%2,%3}, {%4,%5,%6,%7}, {%8,%9}, {%0,%1,%2,%3};"
        : "+f"(d[0]), "+f"(d[1]), "+f"(d[2]), "+f"(d[3])
        : "r"(a[0]), "r"(a[1]), "r"(a[2]), "r"(a[3]), "r"(b0), "r"(b1));
}

// ---------------- hi/lo pack helpers ----------------
__device__ __forceinline__ void wfrag_pack_h(float wx, float wy, uint32_t& whi, uint32_t& wlo) {
    __half h0 = __float2half_rn(wx), h1 = __float2half_rn(wy);
    __half l0 = __float2half_rn(wx - __half2float(h0));
    __half l1 = __float2half_rn(wy - __half2float(h1));
    whi = (uint32_t)__half_as_ushort(h0) | ((uint32_t)__half_as_ushort(h1) << 16);
    wlo = (uint32_t)__half_as_ushort(l0) | ((uint32_t)__half_as_ushort(l1) << 16);
}

// ---------------- prep0 = split_x + split w_ih0 + wfrag0 + state/flag init ------
__global__ void k_prep0(const float* __restrict__ x, const float* __restrict__ w_ih0,
                        const float* __restrict__ w_hh0) {
    const int blk = blockIdx.x, tid = threadIdx.x;
    if (blk < 32768) {                               // x[b][t][d] -> hi/lo [t][b][d]
        int i = blk * 256 + tid;
        int d = i & (Din - 1), t = (i >> 8) & (TT - 1), b = i >> 17;
        float v = x[i];
        bf16 h = __float2bfloat16(v);
        size_t o = ((size_t)t * Bsz + b) * Din + d;
        g_xhi[o] = h;
        g_xlo[o] = __float2bfloat16(v - __bfloat162float(h));
    } else if (blk < 36864) {                        // w_ih0 split
        int i = (blk - 32768) * 256 + tid;
        float v = w_ih0[i];
        bf16 h = __float2bfloat16(v);
        g_w0hi[i] = h;
        g_w0lo[i] = __float2bfloat16(v - __bfloat162float(h));
    } else if (blk < 40960) {                        // wfrag0 (fp16 hi/lo)
        int idx = (blk - 36864) * 256 + tid;         // < 1048576
        int d  = idx >> 19;
        int r  = (idx >> 8) & 2047;
        int k  = (idx & 255) * 2;
        int gg = r >> 9, jj = r & 511;
        int cta = jj >> 3, u = jj & 7;
        int ngl = gg * 8 + u, nt = ngl >> 3, nc = ngl & 7;
        int kt = k >> 4;
        int lane2 = (nc << 2) | ((k & 7) >> 1);
        int reg = ((k & 15) >= 8) ? 1 : 0;
        float2 wv = *(const float2*)(w_hh0 + ((size_t)d * G + r) * Hh + k);
        uint32_t whi, wlo; wfrag_pack_h(wv.x, wv.y, whi, wlo);
        size_t base = ((size_t)d * 64 + cta) * 16384 + ((size_t)(kt * 4 + nt) * 32 + lane2) * 4;
        g_wf0[base + reg]     = whi;
        g_wf0[base + reg + 2] = wlo;
    } else {                                         // state + flag init
        int i = (blk - 40960) * 256 + tid;           // < 131072
        if (i < 65536) (&g_f0[0][0][0])[i] = 0u;
        if (i < 32768) (&g_f1[0][0])[i]    = 0u;
        if (i < 3*64*8) g_flags[i] = 0u;
    }
}

// prep1 = split w_ih1 + wfrag1 (fp16 hi/lo, 64-CTA layout)
__global__ void k_prep1(const float* __restrict__ w_ih1, const float* __restrict__ w_hh1) {
    const int blk = blockIdx.x, tid = threadIdx.x;
    if (blk < 16384) {                               // w_ih1 split (4M elems)
        int i = blk * 256 + tid;
        float v = w_ih1[i];
        bf16 h = __float2bfloat16(v);
        g_w1hi[i] = h;
        g_w1lo[i] = __float2bfloat16(v - __bfloat162float(h));
    } else {                                         // wfrag1
        int idx = (blk - 16384) * 256 + tid;         // < 524288
        int r  = idx >> 8;
        int k  = (idx & 255) * 2;
        int gg = r >> 9, jj = r & 511;
        int cta = jj >> 3, u = jj & 7;
        int ngl = gg * 8 + u, nt = ngl >> 3, nc = ngl & 7;
        int kt = k >> 4;
        int lane2 = (nc << 2) | ((k & 7) >> 1);
        int reg = ((k & 15) >= 8) ? 1 : 0;
        float2 wv = *(const float2*)(w_hh1 + (size_t)r * Hh + k);
        uint32_t whi, wlo; wfrag_pack_h(wv.x, wv.y, whi, wlo);
        size_t base = (size_t)cta * 16384 + ((size_t)(kt * 4 + nt) * 32 + lane2) * 4;
        g_wf1[base + reg]     = whi;
        g_wf1[base + reg + 2] = wlo;
    }
}

// ---------------- HMMA bf16-split projection GEMM (z-dim selects weight slice) --
#define MMSM (2 * 4 * 128 * 40 * 2 + 512)

__device__ __forceinline__ uint4 g_ld4(const bf16* __restrict__ src, int K,
                                       int row, int k0, int q, int rowsv) {
    if (row < rowsv)
        return *reinterpret_cast<const uint4*>(src + (size_t)row * K + k0 + q * 8);
    return make_uint4(0u, 0u, 0u, 0u);
}

__global__ void __launch_bounds__(256) k_mma_gemm(
    const bf16* __restrict__ Ahi, const bf16* __restrict__ Alo,
    const bf16* __restrict__ Bhi, const bf16* __restrict__ Blo,
    const float* __restrict__ bia, const float* __restrict__ bib,
    float* __restrict__ C, int M, int K,
    size_t bzs, size_t czs, int biazs)
{
    const int z = blockIdx.z;
    Bhi += (size_t)z * bzs; Blo += (size_t)z * bzs;
    C   += (size_t)z * czs;
    bia += (size_t)z * biazs; bib += (size_t)z * biazs;

    extern __shared__ __align__(16) char smx[];
    bf16*  sbase = (bf16*)smx;
    float* bsum  = (float*)(smx + 81920);
    const int tid = threadIdx.x, wid = tid >> 5, lane = tid & 31;
    const int bn = blockIdx.x << 7, bm = blockIdx.y << 7;
    const int wm = wid >> 2, wn = wid & 3;
    const int av = (M - bm < 128) ? (M - bm) : 128;

    if (tid < 128) bsum[tid] = bia[bn + tid] + bib[bn + tid];

    const bf16* gAh = Ahi + (size_t)bm * K;
    const bf16* gAl = Alo + (size_t)bm * K;
    const bf16* gBh = Bhi + (size_t)bn * K;
    const bf16* gBl = Blo + (size_t)bn * K;

    const int r0 = tid >> 2, qq = tid & 3;

    {
        uint4 v[4][2];
        v[0][0] = g_ld4(gAh, K, r0, 0, qq, av);  v[0][1] = g_ld4(gAh, K, r0+64, 0, qq, av);
        v[1][0] = g_ld4(gAl, K, r0, 0, qq, av);  v[1][1] = g_ld4(gAl, K, r0+64, 0, qq, av);
        v[2][0] = g_ld4(gBh, K, r0, 0, qq, 128); v[2][1] = g_ld4(gBh, K, r0+64, 0, qq, 128);
        v[3][0] = g_ld4(gBl, K, r0, 0, qq, 128); v[3][1] = g_ld4(gBl, K, r0+64, 0, qq, 128);
#pragma unroll
        for (int t2 = 0; t2 < 4; t2++) {
            bf16* d = sbase + t2 * 5120;
            *reinterpret_cast<uint4*>(d + r0 * 40 + qq * 8)        = v[t2][0];
            *reinterpret_cast<uint4*>(d + (r0 + 64) * 40 + qq * 8) = v[t2][1];
        }
    }
    __syncthreads();

    float acc[4][4][4];
#pragma unroll
    for (int mi = 0; mi < 4; mi++)
#pragma unroll
        for (int ni = 0; ni < 4; ni++)
#pragma unroll
            for (int r = 0; r < 4; r++) acc[mi][ni][r] = 0.0f;

    const uint32_t sbu  = smem_u32(sbase);
    const uint32_t arow = 2u * (((uint32_t)(lane & 15)) * 40u + ((uint32_t)(lane >> 4)) * 8u);
    const int NKB = K >> 5;

    for (int kb = 0; kb < NKB; kb++) {
        uint4 v[4][2];
        const bool pf = (kb + 1 < NKB);
        if (pf) {
            const int k0 = (kb + 1) << 5;
            v[0][0] = g_ld4(gAh, K, r0, k0, qq, av);  v[0][1] = g_ld4(gAh, K, r0+64, k0, qq, av);
            v[1][0] = g_ld4(gAl, K, r0, k0, qq, av);  v[1][1] = g_ld4(gAl, K, r0+64, k0, qq, av);
            v[2][0] = g_ld4(gBh, K, r0, k0, qq, 128); v[2][1] = g_ld4(gBh, K, r0+64, k0, qq, 128);
            v[3][0] = g_ld4(gBl, K, r0, k0, qq, 128); v[3][1] = g_ld4(gBl, K, r0+64, k0, qq, 128);
        }

        const uint32_t base = sbu + ((kb & 1) ? 40960u : 0u);
        const uint32_t aA = base + arow + (uint32_t)wm * 5120u;
        const uint32_t aB = base + 20480u + arow + (uint32_t)wn * 2560u;
#pragma unroll
        for (int kh = 0; kh < 2; kh++) {
            const uint32_t ko = (uint32_t)kh * 32u;
            uint32_t ah[4][4], al_[4][4], bh[2][4], bl_[2][4];
#pragma unroll
            for (int mi = 0; mi < 4; mi++) {
                ldsm4(ah[mi],  aA + (uint32_t)mi * 1280u + ko);
                ldsm4(al_[mi], aA + 10240u + (uint32_t)mi * 1280u + ko);
            }
#pragma unroll
            for (int nj = 0; nj < 2; nj++) {
                ldsm4(bh[nj],  aB + (uint32_t)nj * 1280u + ko);
                ldsm4(bl_[nj], aB + 10240u + (uint32_t)nj * 1280u + ko);
            }
#pragma unroll
            for (int mi = 0; mi < 4; mi++) {
#pragma unroll
                for (int ni = 0; ni < 4; ni++) {
                    const int nj = ni >> 1, sb_ = ni & 1;
                    mma16816(acc[mi][ni], ah[mi],  bh[nj][sb_], bh[nj][sb_ + 2]);
                    mma16816(acc[mi][ni], ah[mi],  bl_[nj][sb_], bl_[nj][sb_ + 2]);
                    mma16816(acc[mi][ni], al_[mi], bh[nj][sb_], bh[nj][sb_ + 2]);
                }
            }
        }

        if (pf) {
            bf16* d0 = sbase + ((kb + 1) & 1) * 20480;
#pragma unroll
            for (int t2 = 0; t2 < 4; t2++) {
                bf16* d = d0 + t2 * 5120;
                *reinterpret_cast<uint4*>(d + r0 * 40 + qq * 8)        = v[t2][0];
                *reinterpret_cast<uint4*>(d + (r0 + 64) * 40 + qq * 8) = v[t2][1];
            }
        }
        __syncthreads();
    }

#pragma unroll
    for (int mi = 0; mi < 4; mi++) {
#pragma unroll
        for (int ni = 0; ni < 4; ni++) {
            const int coll = wn * 32 + ni * 8 + (lane & 3) * 2;
            const int rowa = bm + wm * 64 + mi * 16 + (lane >> 2);
            const float bx = bsum[coll], by = bsum[coll + 1];
            if (rowa < M) {
                float2 p = make_float2(acc[mi][ni][0] + bx, acc[mi][ni][1] + by);
                *reinterpret_cast<float2*>(C + (size_t)rowa * G + bn + coll) = p;
            }
            if (rowa + 8 < M) {
                float2 p = make_float2(acc[mi][ni][2] + bx, acc[mi][ni][3] + by);
                *reinterpret_cast<float2*>(C + (size_t)(rowa + 8) * G + bn + coll) = p;
            }
        }
    }
}

// ---------------- persistent tensor-core LSTM scan, fp16 2-term recurrence ------
// A = h (single fp16), B = w_hh split hi+lo fp16. 2 MMAs per (m2,nt) instead of 3.
template<bool L0>
__global__ void __launch_bounds__(256, 1) k_scan_mma() {
    constexpr int NT = 4, NU = 8, NP = 34;
    __shared__ float gd[4][64][NP];
    __shared__ float c_sm[64][NU];

    const int tid = threadIdx.x, wid = tid >> 5, lane = tid & 31;
    const int kh = wid >> 1, mh = wid & 1;
    const int tig = lane & 3, gid = lane >> 2;

    const int cta = blockIdx.x;                  // 0..63
    const int dir = L0 ? blockIdx.y : 0;
    const int rev = L0 ? dir : 0;
    const int jbase = cta * NU;

    const float* gx = L0 ? (g_gx0 + (size_t)dir * TT * Bsz * G) : g_gx1f;
    const uint4* wf4 = L0 ? ((const uint4*)g_wf0) + ((size_t)dir * 64 + cta) * 4096
                          : ((const uint4*)g_wf1) + (size_t)cta * 4096;
    uint32_t* f0 = L0 ? g_f0[dir][0] : g_f1[0];
    uint32_t* f1 = L0 ? g_f0[dir][1] : g_f1[1];
    unsigned* dom = g_flags + (L0 ? dir * 512 : 1024);
    unsigned* flag_me = dom + cta * 8;
    const unsigned* flag_src = dom + (16 * kh + (lane & 15)) * 8;

    for (int i = tid; i < 64 * NU; i += 256) ((float*)c_sm)[i] = 0.f;

    // pointwise role: thread -> (batch pb, unit pair ppi)
    const int pb  = tid >> 2;
    const int ppi = tid & 3;
    const int jg  = jbase + 2 * ppi;
    const int fc = jg & 15, fr = pb & 15, fmt = pb >> 4, fkt = jg >> 4;
    const int flane = ((fr & 7) << 2) | ((fc & 7) >> 1);
    const int freg  = ((fr >> 3) & 1) | (((fc >> 3) & 1) << 1);
    const int faddr = ((fkt * 4 + fmt) * 32 + flane) * 4 + freg;

    __syncthreads();

    for (int t = 0; t < TT; t++) {
        const int tt = rev ? (TT - 1 - t) : t;
        const uint32_t* fin = (t & 1) ? f1 : f0;
        uint32_t* fout = (t & 1) ? f0 : f1;

        // gate pre-activations (independent of h; issued before the wait)
        float2 pre[4];
        {
            const float* gp = gx + ((size_t)tt * Bsz + pb) * G + jg;
            pre[0] = __ldcs((const float2*)gp);
            pre[1] = __ldcs((const float2*)(gp + 512));
            pre[2] = __ldcs((const float2*)(gp + 1024));
            pre[3] = __ldcs((const float2*)(gp + 1536));
        }

        // wait for this warp's producers to have published h^t
        if (t > 0) {
            unsigned v;
            do {
                asm volatile("ld.acquire.gpu.global.u32 %0, [%1];"
                             : "=r"(v) : "l"(flag_src) : "memory");
            } while (v < (unsigned)t);
            __syncwarp();
        }

        float acc[2][NT][4];
#pragma unroll
        for (int m2 = 0; m2 < 2; m2++)
#pragma unroll
            for (int nt = 0; nt < NT; nt++)
#pragma unroll
                for (int r = 0; r < 4; r++) acc[m2][nt][r] = 0.f;

        // A-fragment double buffer (single fp16 term: one uint4 per slot)
        uint4 cA[2];
        {
            const int kt0 = kh * 8;
#pragma unroll
            for (int m2 = 0; m2 < 2; m2++) {
                const uint32_t* ap = fin + ((size_t)(kt0 * 4 + mh * 2 + m2) * 32 + lane) * 4;
                cA[m2] = __ldcg((const uint4*)ap);
            }
        }

#pragma unroll
        for (int k8 = 0; k8 < 8; k8++) {
            const int kt = kh * 8 + k8;
            uint4 nA[2];
            if (k8 < 7) {
#pragma unroll
                for (int m2 = 0; m2 < 2; m2++) {
                    const uint32_t* ap = fin + ((size_t)((kt + 1) * 4 + mh * 2 + m2) * 32 + lane) * 4;
                    nA[m2] = __ldcg((const uint4*)ap);
                }
            }
            uint4 Bv[NT];
#pragma unroll
            for (int nt = 0; nt < NT; nt++)
                Bv[nt] = __ldg(wf4 + (size_t)(kt * NT + nt) * 32 + lane);
#pragma unroll
            for (int m2 = 0; m2 < 2; m2++) {
                uint32_t a[4] = {cA[m2].x, cA[m2].y, cA[m2].z, cA[m2].w};
#pragma unroll
                for (int nt = 0; nt < NT; nt++) {
                    mma16816h(acc[m2][nt], a, Bv[nt].x, Bv[nt].y);   // h * w_hi
                    mma16816h(acc[m2][nt], a, Bv[nt].z, Bv[nt].w);   // h * w_lo
                }
            }
            if (k8 < 7) {
#pragma unroll
                for (int m2 = 0; m2 < 2; m2++) cA[m2] = nA[m2];
            }
        }

        // dump K-quarter partials to smem
#pragma unroll
        for (int m2 = 0; m2 < 2; m2++) {
            const int rb = (mh * 2 + m2) * 16 + gid;
#pragma unroll
            for (int nt = 0; nt < NT; nt++) {
                const int col = nt * 8 + tig * 2;
                *(float2*)&gd[kh][rb][col]     = make_float2(acc[m2][nt][0], acc[m2][nt][1]);
                *(float2*)&gd[kh][rb + 8][col] = make_float2(acc[m2][nt][2], acc[m2][nt][3]);
            }
        }
        __syncthreads();

        // pointwise + h publish (fp16 pair: one word)
        float hv[2];
        {
#pragma unroll
            for (int uu = 0; uu < 2; uu++) {
                const int u = 2 * ppi + uu;
                float gi = uu ? pre[0].y : pre[0].x;
                float gf = uu ? pre[1].y : pre[1].x;
                float gc = uu ? pre[2].y : pre[2].x;
                float go = uu ? pre[3].y : pre[3].x;
#pragma unroll
                for (int q = 0; q < 4; q++) {
                    gi += gd[q][pb][0 * NU + u];
                    gf += gd[q][pb][1 * NU + u];
                    gc += gd[q][pb][2 * NU + u];
                    go += gd[q][pb][3 * NU + u];
                }
                float cc = sigf(gf) * c_sm[pb][u] + sigf(gi) * tanhfast(gc);
                float hh = sigf(go) * tanhfast(cc);
                c_sm[pb][u] = cc;
                hv[uu] = hh;
            }
            __half2 hp = __floats2half2_rn(hv[0], hv[1]);
            uint32_t hpk = *reinterpret_cast<uint32_t*>(&hp);
            __stcg((unsigned int*)&fout[faddr], hpk);
        }
        __syncthreads();
        if (tid == 0) {
            asm volatile("st.release.gpu.global.u32 [%0], %1;"
                         :: "l"(flag_me), "r"((unsigned)(t + 1)) : "memory");
        }

        // side outputs off the critical path (bf16 hi/lo of exact fp32 h)
        if (L0) {
            bf16 h0h = __float2bfloat16(hv[0]);
            bf16 h1h = __float2bfloat16(hv[1]);
            bf16 h0l = __float2bfloat16(hv[0] - __bfloat162float(h0h));
            bf16 h1l = __float2bfloat16(hv[1] - __bfloat162float(h1h));
            uint32_t whi = (uint32_t)__bfloat16_as_ushort(h0h) | ((uint32_t)__bfloat16_as_ushort(h1h) << 16);
            uint32_t wlo = (uint32_t)__bfloat16_as_ushort(h0l) | ((uint32_t)__bfloat16_as_ushort(h1l) << 16);
            const size_t oo = ((size_t)tt * Bsz + pb) * (2 * Hh) + (size_t)dir * Hh + jg;
            __stcg((unsigned int*)&g_o0hi[oo], whi);
            __stcg((unsigned int*)&g_o0lo[oo], wlo);
        } else {
            g_h1f[(size_t)pb * Hh + jg]     = hv[0];
            g_h1f[(size_t)pb * Hh + jg + 1] = hv[1];
        }
    }
}

// layer1 backward at t=T-1: first step of reverse scan from zero state
__global__ void k_l1bwd() {
    int i = blockIdx.x * 256 + threadIdx.x;
    int b = i >> 9, j = i & 511;
    const float* gxp = g_gx1b + b * G;
    float gi = gxp[j], gc = gxp[2 * Hh + j], go = gxp[3 * Hh + j];
    float c = sigf(gi) * tanhfast(gc);
    float h = sigf(go) * tanhfast(c);
    g_hb[b * Hh + j] = h;
}

// ---------------- layernorm + MLP head ----------------
__global__ void __launch_bounds__(256) k_head(
    const float* __restrict__ ln_g, const float* __restrict__ ln_b,
    const float* __restrict__ w1,   const float* __restrict__ b1,
    const float* __restrict__ w2,   const float* __restrict__ b2,
    float* __restrict__ out)
{
    int b = blockIdx.x, tid = threadIdx.x;
    __shared__ float v[1024];
    __shared__ float red[256];
    for (int i = tid; i < Hh; i += 256) {
        v[i]      = g_h1f[b * Hh + i];
        v[Hh + i] = g_hb[b * Hh + i];
    }
    __syncthreads();
    float s = 0.f;
    for (int i = tid; i < 1024; i += 256) s += v[i];
    red[tid] = s; __syncthreads();
    for (int st = 128; st > 0; st >>= 1) { if (tid < st) red[tid] += red[tid + st]; __syncthreads(); }
    float mu = red[0] * (1.0f / 1024.0f);
    __syncthreads();
    s = 0.f;
    for (int i = tid; i < 1024; i += 256) { float dd = v[i] - mu; s += dd * dd; }
    red[tid] = s; __syncthreads();
    for (int st = 128; st > 0; st >>= 1) { if (tid < st) red[tid] += red[tid + st]; __syncthreads(); }
    float rstd = rsqrtf(red[0] * (1.0f / 1024.0f) + 1e-5f);
    __syncthreads();
    for (int i = tid; i < 1024; i += 256) v[i] = (v[i] - mu) * rstd * ln_g[i] + ln_b[i];
    __syncthreads();
    float part = 0.f;
    for (int jj = tid; jj < Hh; jj += 256) {
        float acc = b1[jj];
        const float* wr = w1 + (size_t)jj * 1024;
#pragma unroll 4
        for (int k2 = 0; k2 < 1024; k2++) acc += v[k2] * wr[k2];
        part += fmaxf(acc, 0.f) * w2[jj];
    }
    red[tid] = part; __syncthreads();
    for (int st = 128; st > 0; st >>= 1) { if (tid < st) red[tid] += red[tid + st]; __syncthreads(); }
    if (tid == 0) out[b] = red[0] + b2[0];
}

// ---------------- launch ----------------
extern "C" void kernel_launch(void* const* d_in, const int* in_sizes, int n_in,
                              void* d_out, int out_size)
{
    (void)in_sizes; (void)n_in; (void)out_size;
    const float* x     = (const float*)d_in[0];
    const float* w_ih0 = (const float*)d_in[1];
    const float* w_hh0 = (const float*)d_in[2];
    const float* b_ih0 = (const float*)d_in[3];
    const float* b_hh0 = (const float*)d_in[4];
    const float* w_ih1 = (const float*)d_in[5];
    const float* w_hh1 = (const float*)d_in[6];
    const float* b_ih1 = (const float*)d_in[7];
    const float* b_hh1 = (const float*)d_in[8];
    const float* ln_g  = (const float*)d_in[9];
    const float* ln_b  = (const float*)d_in[10];
    const float* w1    = (const float*)d_in[11];
    const float* b1    = (const float*)d_in[12];
    const float* w2    = (const float*)d_in[13];
    const float* b2    = (const float*)d_in[14];
    float* out = (float*)d_out;

    cudaFuncSetAttribute(k_mma_gemm, cudaFuncAttributeMaxDynamicSharedMemorySize, MMSM);

    void *p_gx0, *p_gx1f, *p_gx1b;
    void *p_xhi, *p_xlo, *p_o0hi, *p_o0lo, *p_w0hi, *p_w0lo, *p_w1hi, *p_w1lo;
    cudaGetSymbolAddress(&p_gx0, g_gx0);
    cudaGetSymbolAddress(&p_gx1f, g_gx1f);
    cudaGetSymbolAddress(&p_gx1b, g_gx1b);
    cudaGetSymbolAddress(&p_xhi, g_xhi);   cudaGetSymbolAddress(&p_xlo, g_xlo);
    cudaGetSymbolAddress(&p_o0hi, g_o0hi); cudaGetSymbolAddress(&p_o0lo, g_o0lo);
    cudaGetSymbolAddress(&p_w0hi, g_w0hi); cudaGetSymbolAddress(&p_w0lo, g_w0lo);
    cudaGetSymbolAddress(&p_w1hi, g_w1hi); cudaGetSymbolAddress(&p_w1lo, g_w1lo);

    // our launch #3 (0-based) is what ncu -s 5 profiles (2 harness kernels first)
    k_prep0<<<41472, 256>>>(x, w_ih0, w_hh0);                            // 0

    // layer 0 input projections, both directions via gridDim.z=2
    k_mma_gemm<<<dim3(16, 256, 2), 256, MMSM>>>(                         // 1
        (bf16*)p_xhi, (bf16*)p_xlo, (bf16*)p_w0hi, (bf16*)p_w0lo,
        b_ih0, b_hh0, (float*)p_gx0, Bsz * TT, Din,
        (size_t)G * Din, (size_t)TT * Bsz * G, G);

    k_prep1<<<18432, 256>>>(w_ih1, w_hh1);                               // 2

    // layer 0 bidirectional scan  <- profiled
    k_scan_mma<true><<<dim3(64, 2), 256>>>();                            // 3

    // layer 1 fwd projection + bwd projection (only t = T-1)
    k_mma_gemm<<<dim3(16, 256, 1), 256, MMSM>>>(                         // 4
        (bf16*)p_o0hi, (bf16*)p_o0lo, (bf16*)p_w1hi, (bf16*)p_w1lo,
        b_ih1, b_hh1, (float*)p_gx1f, Bsz * TT, 2 * Hh, 0, 0, 0);
    k_mma_gemm<<<dim3(16, 1, 1), 256, MMSM>>>(                           // 5
        (bf16*)p_o0hi + (size_t)(TT - 1) * Bsz * 2 * Hh,
        (bf16*)p_o0lo + (size_t)(TT - 1) * Bsz * 2 * Hh,
        (bf16*)p_w1hi + (size_t)G * 2 * Hh, (bf16*)p_w1lo + (size_t)G * 2 * Hh,
        b_ih1 + G, b_hh1 + G, (float*)p_gx1b, Bsz, 2 * Hh, 0, 0, 0);

    // layer 1 forward scan (64 CTAs, NU=8)
    k_scan_mma<false><<<64, 256>>>();                                    // 6

    k_l1bwd<<<128, 256>>>();                                             // 7
    k_head<<<64, 256>>>(ln_g, ln_b, w1, b1, w2, b2, out);                // 8
}